// round 1
// baseline (speedup 1.0000x reference)
#include <cuda_runtime.h>

#define BSZ 8
#define HD  512
#define PD  128
#define LD  8192
#define M2  256   // 2*P (re rows then im rows)

// Scratch (no allocations allowed): Bu, then xs in-place after scan.
__device__ __align__(128) float g_bu[(size_t)BSZ * M2 * LD];   // 64 MB
__device__ __align__(128) float g_bcat[M2 * HD];               // [2P][H]
__device__ __align__(128) float g_ccat[HD * M2];               // [H][2P] (2*C_re | -2*C_im)
__device__ float g_lam_re[PD];
__device__ float g_lam_im[PD];

typedef unsigned long long u64;

__device__ __forceinline__ void fma2(u64& d, u64 a, u64 b) {
    asm("fma.rn.f32x2 %0, %1, %2, %0;" : "+l"(d) : "l"(a), "l"(b));
}
__device__ __forceinline__ u64 dup2(float x) {
    u64 r; asm("mov.b64 %0, {%1, %1};" : "=l"(r) : "f"(x)); return r;
}
__device__ __forceinline__ float2 up2(u64 v) {
    float2 f; asm("mov.b64 {%0, %1}, %2;" : "=f"(f.x), "=f"(f.y) : "l"(v)); return f;
}
__device__ __forceinline__ float gelu_exact(float x) {
    return 0.5f * x * (1.0f + erff(x * 0.70710678118654752f));
}

// ---------------------------------------------------------------------------
// Precompute: Lambda_bar, Bcat = [Re(B_bar); Im(B_bar)], Ccat = [2C_re | -2C_im]
// 65536 threads; each handles one (p,h) for Bcat and one (h,p) for Ccat.
// ---------------------------------------------------------------------------
__global__ void precompute_kernel(const float* __restrict__ lre,
                                  const float* __restrict__ lim,
                                  const float* __restrict__ Bp,
                                  const float* __restrict__ Cp,
                                  const float* __restrict__ ls) {
    int idx = blockIdx.x * blockDim.x + threadIdx.x;   // [0, 65536)
    // --- Bcat part: p = idx>>9, h = idx&511
    {
        int p = idx >> 9, h = idx & 511;
        float ar = lre[p], ai = lim[p];
        float st = expf(ls[p]);
        float er = expf(ar * st);
        float sb, cb; sincosf(ai * st, &sb, &cb);
        float lbr = er * cb, lbi = er * sb;            // Lambda_bar
        float nr = lbr - 1.0f, ni = lbi;
        float den = ar * ar + ai * ai;
        float cr = (nr * ar + ni * ai) / den;          // (lbar-1)/Lambda
        float ci = (ni * ar - nr * ai) / den;
        float btr = Bp[(p * HD + h) * 2 + 0];
        float bti = Bp[(p * HD + h) * 2 + 1];
        g_bcat[p * HD + h]        = cr * btr - ci * bti;
        g_bcat[(p + PD) * HD + h] = cr * bti + ci * btr;
    }
    // --- Lambda_bar store (first 128 threads)
    if (idx < PD) {
        float ar = lre[idx], ai = lim[idx];
        float st = expf(ls[idx]);
        float er = expf(ar * st);
        float sb, cb; sincosf(ai * st, &sb, &cb);
        g_lam_re[idx] = er * cb;
        g_lam_im[idx] = er * sb;
    }
    // --- Ccat part: h = idx>>7, p = idx&127
    {
        int h = idx >> 7, p = idx & 127;
        g_ccat[h * M2 + p]      =  2.0f * Cp[(h * PD + p) * 2 + 0];
        g_ccat[h * M2 + p + PD] = -2.0f * Cp[(h * PD + p) * 2 + 1];
    }
}

// ---------------------------------------------------------------------------
// Tiled fp32 GEMM with f32x2 packed FFMA.
//   SECOND=false: Bu[b][m][l]  = sum_h Bcat[m][h] * u[b][h][l]       (K=512, Mtot=256)
//   SECOND=true : out[b][h][l] = gelu( sum_m Ccat[h][m]*xs[b][m][l]
//                                      + D[h]*u[b][h][l] )           (K=256, Mtot=512)
// Tile 128x128, 256 threads, 8x8 micro-tile per thread.
// ---------------------------------------------------------------------------
template<bool SECOND>
__global__ __launch_bounds__(256)
void gemm_kernel(const float* __restrict__ Uin,
                 float* __restrict__ Dout,
                 const float* __restrict__ Dvec) {
    constexpr int KDIM = SECOND ? M2 : HD;
    constexpr int AS_STRIDE = 133;

    __shared__ float As[16 * AS_STRIDE];
    __shared__ float Bs[16 * 128];

    const float* A   = SECOND ? g_ccat : g_bcat;
    const float* Bm  = SECOND ? (const float*)g_bu : Uin;
    float*       Cm  = SECOND ? Dout : g_bu;

    int tid = threadIdx.x;
    int tx = tid & 15, ty = tid >> 4;
    int m0 = blockIdx.y * 128;
    int n0 = blockIdx.x * 128;
    int z  = blockIdx.z;

    const size_t Boff = (size_t)z * KDIM * LD;
    const int    Mtot = gridDim.y * 128;
    const size_t Coff = (size_t)z * Mtot * LD;

    u64 acc[8][4];
    #pragma unroll
    for (int r = 0; r < 8; r++)
        #pragma unroll
        for (int c = 0; c < 4; c++) acc[r][c] = 0ULL;

    const int arow = tid >> 2;        // 0..63
    const int acol = (tid & 3) * 4;   // 0,4,8,12
    const int brow = tid >> 5;        // 0..7
    const int bcol = (tid & 31) * 4;  // 0..124

    for (int k0 = 0; k0 < KDIM; k0 += 16) {
        #pragma unroll
        for (int r = 0; r < 2; r++) {
            int row = arow + r * 64;
            float4 av = *(const float4*)&A[(size_t)(m0 + row) * KDIM + k0 + acol];
            As[(acol + 0) * AS_STRIDE + row] = av.x;
            As[(acol + 1) * AS_STRIDE + row] = av.y;
            As[(acol + 2) * AS_STRIDE + row] = av.z;
            As[(acol + 3) * AS_STRIDE + row] = av.w;
        }
        #pragma unroll
        for (int r = 0; r < 2; r++) {
            int row = brow + r * 8;
            float4 bv = *(const float4*)&Bm[Boff + (size_t)(k0 + row) * LD + n0 + bcol];
            *(float4*)&Bs[row * 128 + bcol] = bv;
        }
        __syncthreads();

        #pragma unroll
        for (int kk = 0; kk < 16; kk++) {
            const float* ap = &As[kk * AS_STRIDE + ty * 8];
            const u64*   bp = (const u64*)&Bs[kk * 128 + tx * 8];
            u64 B0 = bp[0], B1 = bp[1], B2 = bp[2], B3 = bp[3];
            #pragma unroll
            for (int r = 0; r < 8; r++) {
                u64 a2 = dup2(ap[r]);
                fma2(acc[r][0], a2, B0);
                fma2(acc[r][1], a2, B1);
                fma2(acc[r][2], a2, B2);
                fma2(acc[r][3], a2, B3);
            }
        }
        __syncthreads();
    }

    // Epilogue
    #pragma unroll
    for (int r = 0; r < 8; r++) {
        int row = m0 + ty * 8 + r;
        size_t off = Coff + (size_t)row * LD + n0 + tx * 8;
        float2 p0 = up2(acc[r][0]), p1 = up2(acc[r][1]);
        float2 p2 = up2(acc[r][2]), p3 = up2(acc[r][3]);
        float v0 = p0.x, v1 = p0.y, v2 = p1.x, v3 = p1.y;
        float v4 = p2.x, v5 = p2.y, v6 = p3.x, v7 = p3.y;
        if (SECOND) {
            float d = Dvec[row];
            float4 u0 = *(const float4*)&Uin[off];
            float4 u1 = *(const float4*)&Uin[off + 4];
            v0 = gelu_exact(v0 + d * u0.x);
            v1 = gelu_exact(v1 + d * u0.y);
            v2 = gelu_exact(v2 + d * u0.z);
            v3 = gelu_exact(v3 + d * u0.w);
            v4 = gelu_exact(v4 + d * u1.x);
            v5 = gelu_exact(v5 + d * u1.y);
            v6 = gelu_exact(v6 + d * u1.z);
            v7 = gelu_exact(v7 + d * u1.w);
        }
        *(float4*)&Cm[off]     = make_float4(v0, v1, v2, v3);
        *(float4*)&Cm[off + 4] = make_float4(v4, v5, v6, v7);
    }
}

// ---------------------------------------------------------------------------
// Scan: x_l = a * x_{l-1} + b_l, complex diagonal a per channel.
// One block per (b,p) channel; chunks of 2048 staged in smem; thread segments
// of 8; Hillis-Steele over the 256 segment carries with constant multipliers
// m_k = (a^8)^(2^k).
// ---------------------------------------------------------------------------
__global__ __launch_bounds__(256)
void scan_kernel() {
    int ch = blockIdx.x;            // 0..1023
    int b = ch >> 7, p = ch & 127;
    const float ar = g_lam_re[p];
    const float ai = g_lam_im[p];

    float* bre = g_bu + ((size_t)b * M2 + p) * LD;
    float* bim = g_bu + ((size_t)b * M2 + p + PD) * LD;

    __shared__ float sre[2112], sim[2112];   // 2048 + pad (i + (i>>5))
    __shared__ float vre[256], vim[256];
    __shared__ float carry_re, carry_im;

    int t = threadIdx.x;
    if (t == 0) { carry_re = 0.0f; carry_im = 0.0f; }

    // m_k = (a^8)^(2^k), k = 0..7
    float mr[8], mi[8];
    {
        float xr = ar, xi = ai;
        #pragma unroll
        for (int s = 0; s < 3; s++) {         // a -> a^8
            float nr = xr * xr - xi * xi;
            float ni = 2.0f * xr * xi;
            xr = nr; xi = ni;
        }
        mr[0] = xr; mi[0] = xi;
        #pragma unroll
        for (int k = 1; k < 8; k++) {
            mr[k] = mr[k-1] * mr[k-1] - mi[k-1] * mi[k-1];
            mi[k] = 2.0f * mr[k-1] * mi[k-1];
        }
    }
    __syncthreads();

    const int base = t * 8;
    for (int c0 = 0; c0 < LD; c0 += 2048) {
        // stage chunk (coalesced gmem, padded smem)
        for (int j = t; j < 2048; j += 256) {
            sre[j + (j >> 5)] = bre[c0 + j];
            sim[j + (j >> 5)] = bim[c0 + j];
        }
        __syncthreads();

        // pass 1: per-thread segment end (thread 0 seeds with the chunk carry)
        float er = 0.0f, ei = 0.0f;
        if (t == 0) { er = carry_re; ei = carry_im; }
        #pragma unroll
        for (int i = 0; i < 8; i++) {
            int idx = base + i; idx += idx >> 5;
            float br = sre[idx], bi = sim[idx];
            float nr = ar * er - ai * ei + br;
            float ni = ar * ei + ai * er + bi;
            er = nr; ei = ni;
        }
        vre[t] = er; vim[t] = ei;
        __syncthreads();

        // Hillis-Steele inclusive scan over 256 carries
        #pragma unroll
        for (int k = 0; k < 8; k++) {
            int off = 1 << k;
            float pr = 0.0f, pi = 0.0f;
            if (t >= off) { pr = vre[t - off]; pi = vim[t - off]; }
            __syncthreads();
            if (t >= off) {
                vre[t] += mr[k] * pr - mi[k] * pi;
                vim[t] += mr[k] * pi + mi[k] * pr;
            }
            __syncthreads();
        }

        // pass 2: replay each segment with its true carry-in, overwrite smem
        float xr, xi;
        if (t == 0) { xr = carry_re; xi = carry_im; }
        else        { xr = vre[t-1]; xi = vim[t-1]; }
        #pragma unroll
        for (int i = 0; i < 8; i++) {
            int idx = base + i; idx += idx >> 5;
            float br = sre[idx], bi = sim[idx];
            float nr = ar * xr - ai * xi + br;
            float ni = ar * xi + ai * xr + bi;
            xr = nr; xi = ni;
            sre[idx] = xr; sim[idx] = xi;
        }
        __syncthreads();

        if (t == 0) { carry_re = vre[255]; carry_im = vim[255]; }
        for (int j = t; j < 2048; j += 256) {
            bre[c0 + j] = sre[j + (j >> 5)];
            bim[c0 + j] = sim[j + (j >> 5)];
        }
        __syncthreads();
    }
}

// ---------------------------------------------------------------------------
extern "C" void kernel_launch(void* const* d_in, const int* in_sizes, int n_in,
                              void* d_out, int out_size) {
    const float* u   = (const float*)d_in[0];   // (8,1,512,1,8192)
    const float* lre = (const float*)d_in[1];   // (128,)
    const float* lim = (const float*)d_in[2];   // (128,)
    const float* B   = (const float*)d_in[3];   // (128,512,2)
    const float* C   = (const float*)d_in[4];   // (512,128,2)
    const float* D   = (const float*)d_in[5];   // (512,)
    const float* ls  = (const float*)d_in[6];   // (128,1)
    float* out = (float*)d_out;                 // (8,1,512,1,8192)

    precompute_kernel<<<256, 256>>>(lre, lim, B, C, ls);
    gemm_kernel<false><<<dim3(64, 2, BSZ), 256>>>(u, nullptr, nullptr);
    scan_kernel<<<1024, 256>>>();
    gemm_kernel<true><<<dim3(64, 4, BSZ), 256>>>(u, out, D);
}

// round 5
// speedup vs baseline: 1.8840x; 1.8840x over previous
#include <cuda_runtime.h>
#include <cuda_bf16.h>
#include <cstdint>

#define BSZN 8
#define HD   512
#define PD   128
#define LEN  8192
#define M2   256

// ---------------- scratch (no allocations allowed) ----------------
__device__ __align__(128) float g_bu[(size_t)BSZN * M2 * LEN];   // 64 MB: Bu -> xs in place
__device__ __align__(128) __nv_bfloat16 g_w1hi[M2 * HD];
__device__ __align__(128) __nv_bfloat16 g_w1lo[M2 * HD];
__device__ __align__(128) __nv_bfloat16 g_w2hi[HD * M2];
__device__ __align__(128) __nv_bfloat16 g_w2lo[HD * M2];
__device__ float g_lam_re[PD];
__device__ float g_lam_im[PD];

// ---------------- helpers ----------------
__device__ __forceinline__ uint32_t smem_u32(const void* p) {
    uint32_t a;
    asm("{ .reg .u64 t; cvta.to.shared.u64 t, %1; cvt.u32.u64 %0, t; }" : "=r"(a) : "l"(p));
    return a;
}
__device__ __forceinline__ float gelu_exact(float x) {
    return 0.5f * x * (1.0f + erff(x * 0.70710678118654752f));
}
__device__ __forceinline__ void ldsm_x4(uint32_t (&r)[4], uint32_t addr) {
    asm volatile("ldmatrix.sync.aligned.m8n8.x4.shared.b16 {%0,%1,%2,%3}, [%4];"
                 : "=r"(r[0]), "=r"(r[1]), "=r"(r[2]), "=r"(r[3]) : "r"(addr));
}
__device__ __forceinline__ void ldsm_x4_t(uint32_t (&r)[4], uint32_t addr) {
    asm volatile("ldmatrix.sync.aligned.m8n8.x4.trans.shared.b16 {%0,%1,%2,%3}, [%4];"
                 : "=r"(r[0]), "=r"(r[1]), "=r"(r[2]), "=r"(r[3]) : "r"(addr));
}
__device__ __forceinline__ void mma_bf16(float (&c)[4], const uint32_t (&a)[4],
                                         const uint32_t* b) {
    asm volatile("mma.sync.aligned.m16n8k16.row.col.f32.bf16.bf16.f32 "
                 "{%0,%1,%2,%3},{%4,%5,%6,%7},{%8,%9},{%0,%1,%2,%3};"
                 : "+f"(c[0]), "+f"(c[1]), "+f"(c[2]), "+f"(c[3])
                 : "r"(a[0]), "r"(a[1]), "r"(a[2]), "r"(a[3]), "r"(b[0]), "r"(b[1]));
}
__device__ __forceinline__ uint32_t pack_bf16x2(__nv_bfloat16 lo, __nv_bfloat16 hi) {
    return ((uint32_t)__bfloat16_as_ushort(hi) << 16) | (uint32_t)__bfloat16_as_ushort(lo);
}

// ---------------------------------------------------------------------------
// Precompute: Lambda_bar; weights pre-split into bf16 hi/lo.
//   W1 = [Re(B_bar); Im(B_bar)]  (2P x H)   W2 = [2*C_re | -2*C_im] (H x 2P)
// ---------------------------------------------------------------------------
__global__ void precompute_kernel(const float* __restrict__ lre,
                                  const float* __restrict__ lim,
                                  const float* __restrict__ Bp,
                                  const float* __restrict__ Cp,
                                  const float* __restrict__ ls) {
    int idx = blockIdx.x * blockDim.x + threadIdx.x;   // [0, 65536)
    {   // W1: p = idx>>9, hcol = idx&511
        int p = idx >> 9, hcol = idx & 511;
        float ar = lre[p], ai = lim[p];
        float st = expf(ls[p]);
        float er = expf(ar * st);
        float sb, cb; sincosf(ai * st, &sb, &cb);
        float lbr = er * cb, lbi = er * sb;
        float nr = lbr - 1.0f, ni = lbi;
        float den = ar * ar + ai * ai;
        float cr = (nr * ar + ni * ai) / den;
        float ci = (ni * ar - nr * ai) / den;
        float btr = Bp[(p * HD + hcol) * 2 + 0];
        float bti = Bp[(p * HD + hcol) * 2 + 1];
        float vre = cr * btr - ci * bti;
        float vim = cr * bti + ci * btr;
        __nv_bfloat16 h0 = __float2bfloat16_rn(vre);
        g_w1hi[p * HD + hcol] = h0;
        g_w1lo[p * HD + hcol] = __float2bfloat16_rn(vre - __bfloat162float(h0));
        __nv_bfloat16 h1 = __float2bfloat16_rn(vim);
        g_w1hi[(p + PD) * HD + hcol] = h1;
        g_w1lo[(p + PD) * HD + hcol] = __float2bfloat16_rn(vim - __bfloat162float(h1));
    }
    if (idx < PD) {
        float ar = lre[idx], ai = lim[idx];
        float st = expf(ls[idx]);
        float er = expf(ar * st);
        float sb, cb; sincosf(ai * st, &sb, &cb);
        g_lam_re[idx] = er * cb;
        g_lam_im[idx] = er * sb;
    }
    {   // W2: hrow = idx>>7, p = idx&127
        int hrow = idx >> 7, p = idx & 127;
        float vre =  2.0f * Cp[(hrow * PD + p) * 2 + 0];
        float vim = -2.0f * Cp[(hrow * PD + p) * 2 + 1];
        __nv_bfloat16 h0 = __float2bfloat16_rn(vre);
        g_w2hi[hrow * M2 + p] = h0;
        g_w2lo[hrow * M2 + p] = __float2bfloat16_rn(vre - __bfloat162float(h0));
        __nv_bfloat16 h1 = __float2bfloat16_rn(vim);
        g_w2hi[hrow * M2 + p + PD] = h1;
        g_w2lo[hrow * M2 + p + PD] = __float2bfloat16_rn(vim - __bfloat162float(h1));
    }
}

// ---------------------------------------------------------------------------
// mma.sync bf16 GEMM with 3-product split (hh + hl + lh).
// CTA tile 128x128, K-chunks of 32, 8 warps (4m x 2n), warp tile 32x64.
// SMEM per chunk buffer: Ahi(8K) Alo(8K) Bhi(8K) Blo(8K) = 32KB; double = 64KB.
//   SECOND=false: Bu[b][m][l]  = sum_h W1[m][h] * u[b][h][l]      (K=512, Mtot=256)
//   SECOND=true : out[b][h][l] = gelu(sum_m W2[h][m]*xs[b][m][l] + D[h]*u)   (K=256)
// ---------------------------------------------------------------------------
#define ABUF 8192
#define BUFSZ 32768
#define GSMEM 65536

template<bool SECOND>
__global__ __launch_bounds__(256)
void mgemm_kernel(const float* __restrict__ uin,
                  float* __restrict__ outp,
                  const float* __restrict__ Dvec) {
    constexpr int KDIM = SECOND ? M2 : HD;
    constexpr int NCH  = KDIM / 32;

    extern __shared__ __align__(128) char smem[];
    const uint32_t sbase = smem_u32(smem);

    const int tid  = threadIdx.x;
    const int wid  = tid >> 5;
    const int lane = tid & 31;
    const int warp_m = wid & 3;
    const int warp_n = wid >> 2;
    const int m0 = blockIdx.x * 128;
    const int n0 = blockIdx.y * 128;
    const int z  = blockIdx.z;

    const __nv_bfloat16* Whi = SECOND ? g_w2hi : g_w1hi;
    const __nv_bfloat16* Wlo = SECOND ? g_w2lo : g_w1lo;
    const float* Bsrc = SECOND ? (const float*)g_bu : uin;
    float*       Cdst = SECOND ? outp : (float*)g_bu;
    const size_t Bofs = (size_t)z * KDIM * LEN;
    const size_t Cofs = (size_t)z * (SECOND ? HD : M2) * LEN;

    // staging maps
    const int sAr = tid >> 1, sAh = tid & 1;       // A: row, k-half(16)
    const int sBk = tid >> 3, sBn = tid & 7;       // B: k-row, 16-wide n group

    uint4 pAh[2], pAl[2];
    float4 pB[4];

    auto load_next = [&](int k0) {
        const uint4* ph = (const uint4*)(Whi + (size_t)(m0 + sAr) * KDIM + k0 + sAh * 16);
        pAh[0] = ph[0]; pAh[1] = ph[1];
        const uint4* pl = (const uint4*)(Wlo + (size_t)(m0 + sAr) * KDIM + k0 + sAh * 16);
        pAl[0] = pl[0]; pAl[1] = pl[1];
        const float4* pb = (const float4*)(Bsrc + Bofs + (size_t)(k0 + sBk) * LEN + n0 + sBn * 16);
        pB[0] = pb[0]; pB[1] = pb[1]; pB[2] = pb[2]; pB[3] = pb[3];
    };

    auto stage = [&](uint32_t bb) {
        // --- A tiles (bf16, pre-split). rows of 64B, swizzle c ^= (r>>1)&3
        {
            const int r = sAr;
            const int swz = (r >> 1) & 3;
            const int c0 = sAh * 2;
            char* rowp = smem + bb + r * 64;
            *(uint4*)(rowp + (((c0 + 0) ^ swz) << 4))        = pAh[0];
            *(uint4*)(rowp + (((c0 + 1) ^ swz) << 4))        = pAh[1];
            *(uint4*)(rowp + ABUF + (((c0 + 0) ^ swz) << 4)) = pAl[0];
            *(uint4*)(rowp + ABUF + (((c0 + 1) ^ swz) << 4)) = pAl[1];
        }
        // --- B tile: fp32 -> bf16 hi/lo split. rows of 256B, swizzle c ^= k&7
        {
            float xs[16] = { pB[0].x, pB[0].y, pB[0].z, pB[0].w,
                             pB[1].x, pB[1].y, pB[1].z, pB[1].w,
                             pB[2].x, pB[2].y, pB[2].z, pB[2].w,
                             pB[3].x, pB[3].y, pB[3].z, pB[3].w };
            uint32_t hw[8], lw[8];
            #pragma unroll
            for (int j = 0; j < 8; j++) {
                float x0 = xs[2*j], x1 = xs[2*j+1];
                __nv_bfloat16 h0 = __float2bfloat16_rn(x0);
                __nv_bfloat16 h1 = __float2bfloat16_rn(x1);
                __nv_bfloat16 l0 = __float2bfloat16_rn(x0 - __bfloat162float(h0));
                __nv_bfloat16 l1 = __float2bfloat16_rn(x1 - __bfloat162float(h1));
                hw[j] = pack_bf16x2(h0, h1);
                lw[j] = pack_bf16x2(l0, l1);
            }
            const int k = sBk;
            const int swz = k & 7;
            char* rowp = smem + bb + 2 * ABUF + k * 256;
            uint32_t o0 = ((sBn * 2 + 0) ^ swz) << 4;
            uint32_t o1 = ((sBn * 2 + 1) ^ swz) << 4;
            *(uint4*)(rowp + o0)        = make_uint4(hw[0], hw[1], hw[2], hw[3]);
            *(uint4*)(rowp + o1)        = make_uint4(hw[4], hw[5], hw[6], hw[7]);
            *(uint4*)(rowp + ABUF + o0) = make_uint4(lw[0], lw[1], lw[2], lw[3]);
            *(uint4*)(rowp + ABUF + o1) = make_uint4(lw[4], lw[5], lw[6], lw[7]);
        }
    };

    float acc[2][8][4];
    #pragma unroll
    for (int a = 0; a < 2; a++)
        #pragma unroll
        for (int b = 0; b < 8; b++)
            #pragma unroll
            for (int c = 0; c < 4; c++) acc[a][b][c] = 0.0f;

    // ldmatrix lane address components (fixed)
    const int lrow8 = (lane & 7) + ((lane >> 3) & 1) * 8;   // 0..15
    const int lhalf = (lane >> 4) & 1;                      // 0/1

    auto compute = [&](uint32_t bb) {
        #pragma unroll
        for (int ks = 0; ks < 2; ks++) {
            uint32_t Ah[2][4], Al[2][4];
            #pragma unroll
            for (int mt = 0; mt < 2; mt++) {
                int row = warp_m * 32 + mt * 16 + lrow8;
                int c = ks * 2 + lhalf;
                uint32_t addr = sbase + bb + row * 64 + ((c ^ ((row >> 1) & 3)) << 4);
                ldsm_x4(Ah[mt], addr);
                ldsm_x4(Al[mt], addr + ABUF);
            }
            #pragma unroll
            for (int nt = 0; nt < 4; nt++) {
                int krow = ks * 16 + lrow8;
                int noff = warp_n * 64 + nt * 16 + lhalf * 8;
                int c = noff >> 3;
                uint32_t addr = sbase + bb + 2 * ABUF + krow * 256 +
                                ((c ^ (krow & 7)) << 4);
                uint32_t Bh[4], Bl[4];
                ldsm_x4_t(Bh, addr);
                ldsm_x4_t(Bl, addr + ABUF);
                #pragma unroll
                for (int mt = 0; mt < 2; mt++) {
                    mma_bf16(acc[mt][2*nt + 0], Ah[mt], &Bh[0]);
                    mma_bf16(acc[mt][2*nt + 0], Ah[mt], &Bl[0]);
                    mma_bf16(acc[mt][2*nt + 0], Al[mt], &Bh[0]);
                    mma_bf16(acc[mt][2*nt + 1], Ah[mt], &Bh[2]);
                    mma_bf16(acc[mt][2*nt + 1], Ah[mt], &Bl[2]);
                    mma_bf16(acc[mt][2*nt + 1], Al[mt], &Bh[2]);
                }
            }
        }
    };

    load_next(0);
    for (int i = 0; i < NCH; i++) {
        const uint32_t bb = (uint32_t)(i & 1) * BUFSZ;
        stage(bb);
        __syncthreads();
        if (i + 1 < NCH) load_next((i + 1) * 32);
        compute(bb);
    }

    // ---------------- epilogue ----------------
    const int g = lane >> 2, t4 = lane & 3;
    #pragma unroll
    for (int mt = 0; mt < 2; mt++) {
        #pragma unroll
        for (int nt8 = 0; nt8 < 8; nt8++) {
            int col = n0 + warp_n * 64 + nt8 * 8 + t4 * 2;
            #pragma unroll
            for (int h = 0; h < 2; h++) {
                int row = m0 + warp_m * 32 + mt * 16 + g + h * 8;
                size_t off = Cofs + (size_t)row * LEN + col;
                float v0 = acc[mt][nt8][2*h + 0];
                float v1 = acc[mt][nt8][2*h + 1];
                if (SECOND) {
                    float d = __ldg(&Dvec[row]);
                    float2 uu = *(const float2*)&uin[(size_t)z * HD * LEN +
                                                     (size_t)row * LEN + col];
                    v0 = gelu_exact(v0 + d * uu.x);
                    v1 = gelu_exact(v1 + d * uu.y);
                }
                float2 st; st.x = v0; st.y = v1;
                *(float2*)&Cdst[off] = st;
            }
        }
    }
}

// ---------------------------------------------------------------------------
// Scan: x_l = a*x_{l-1} + b_l, complex diagonal, one block per (b,p) channel.
// ---------------------------------------------------------------------------
__global__ __launch_bounds__(256)
void scan_kernel() {
    int ch = blockIdx.x;
    int b = ch >> 7, p = ch & 127;
    const float ar = g_lam_re[p];
    const float ai = g_lam_im[p];

    float* bre = g_bu + ((size_t)b * M2 + p) * LEN;
    float* bim = g_bu + ((size_t)b * M2 + p + PD) * LEN;

    __shared__ float sre[2112], sim[2112];
    __shared__ float vre[256], vim[256];
    __shared__ float carry_re, carry_im;

    int t = threadIdx.x;
    if (t == 0) { carry_re = 0.0f; carry_im = 0.0f; }

    float mr[8], mi[8];
    {
        float xr = ar, xi = ai;
        #pragma unroll
        for (int s = 0; s < 3; s++) {
            float nr = xr * xr - xi * xi;
            float ni = 2.0f * xr * xi;
            xr = nr; xi = ni;
        }
        mr[0] = xr; mi[0] = xi;
        #pragma unroll
        for (int k = 1; k < 8; k++) {
            mr[k] = mr[k-1] * mr[k-1] - mi[k-1] * mi[k-1];
            mi[k] = 2.0f * mr[k-1] * mi[k-1];
        }
    }
    __syncthreads();

    const int base = t * 8;
    for (int c0 = 0; c0 < LEN; c0 += 2048) {
        for (int j = t; j < 2048; j += 256) {
            sre[j + (j >> 5)] = bre[c0 + j];
            sim[j + (j >> 5)] = bim[c0 + j];
        }
        __syncthreads();

        float er = 0.0f, ei = 0.0f;
        if (t == 0) { er = carry_re; ei = carry_im; }
        #pragma unroll
        for (int i = 0; i < 8; i++) {
            int idx = base + i; idx += idx >> 5;
            float br = sre[idx], bi = sim[idx];
            float nr = ar * er - ai * ei + br;
            float ni = ar * ei + ai * er + bi;
            er = nr; ei = ni;
        }
        vre[t] = er; vim[t] = ei;
        __syncthreads();

        #pragma unroll
        for (int k = 0; k < 8; k++) {
            int off = 1 << k;
            float pr = 0.0f, pi = 0.0f;
            if (t >= off) { pr = vre[t - off]; pi = vim[t - off]; }
            __syncthreads();
            if (t >= off) {
                vre[t] += mr[k] * pr - mi[k] * pi;
                vim[t] += mr[k] * pi + mi[k] * pr;
            }
            __syncthreads();
        }

        float xr, xi;
        if (t == 0) { xr = carry_re; xi = carry_im; }
        else        { xr = vre[t-1]; xi = vim[t-1]; }
        #pragma unroll
        for (int i = 0; i < 8; i++) {
            int idx = base + i; idx += idx >> 5;
            float br = sre[idx], bi = sim[idx];
            float nr = ar * xr - ai * xi + br;
            float ni = ar * xi + ai * xr + bi;
            xr = nr; xi = ni;
            sre[idx] = xr; sim[idx] = xi;
        }
        __syncthreads();

        if (t == 0) { carry_re = vre[255]; carry_im = vim[255]; }
        for (int j = t; j < 2048; j += 256) {
            bre[c0 + j] = sre[j + (j >> 5)];
            bim[c0 + j] = sim[j + (j >> 5)];
        }
        __syncthreads();
    }
}

// ---------------------------------------------------------------------------
extern "C" void kernel_launch(void* const* d_in, const int* in_sizes, int n_in,
                              void* d_out, int out_size) {
    const float* u   = (const float*)d_in[0];   // (8,1,512,1,8192)
    const float* lre = (const float*)d_in[1];
    const float* lim = (const float*)d_in[2];
    const float* B   = (const float*)d_in[3];
    const float* C   = (const float*)d_in[4];
    const float* D   = (const float*)d_in[5];
    const float* ls  = (const float*)d_in[6];
    float* out = (float*)d_out;

    cudaFuncSetAttribute(mgemm_kernel<false>,
                         cudaFuncAttributeMaxDynamicSharedMemorySize, GSMEM);
    cudaFuncSetAttribute(mgemm_kernel<true>,
                         cudaFuncAttributeMaxDynamicSharedMemorySize, GSMEM);

    precompute_kernel<<<256, 256>>>(lre, lim, B, C, ls);
    mgemm_kernel<false><<<dim3(2, 64, BSZN), 256, GSMEM>>>(u, nullptr, nullptr);
    scan_kernel<<<1024, 256>>>();
    mgemm_kernel<true><<<dim3(4, 64, BSZN), 256, GSMEM>>>(u, out, D);
}

// round 8
// speedup vs baseline: 2.3085x; 1.2253x over previous
#include <cuda_runtime.h>
#include <cuda_bf16.h>
#include <cstdint>

#define BSZN 8
#define HD   512
#define PD   128
#define LEN  8192
#define M2   256

// ---------------- scratch (no allocations allowed) ----------------
__device__ __align__(128) float g_bu[(size_t)BSZN * M2 * LEN];          // 64 MB (Bu, fp32)
__device__ __align__(128) __nv_bfloat16 g_uhi[(size_t)BSZN * HD * LEN]; // 32 MB
__device__ __align__(128) __nv_bfloat16 g_ulo[(size_t)BSZN * HD * LEN]; // 32 MB
__device__ __align__(128) __nv_bfloat16 g_xhi[(size_t)BSZN * M2 * LEN]; // 32 MB
__device__ __align__(128) __nv_bfloat16 g_xlo[(size_t)BSZN * M2 * LEN]; // 32 MB
__device__ __align__(128) __nv_bfloat16 g_w1hi[M2 * HD];
__device__ __align__(128) __nv_bfloat16 g_w1lo[M2 * HD];
__device__ __align__(128) __nv_bfloat16 g_w2hi[HD * M2];
__device__ __align__(128) __nv_bfloat16 g_w2lo[HD * M2];
__device__ float g_lam_re[PD];
__device__ float g_lam_im[PD];

// ---------------- helpers ----------------
__device__ __forceinline__ uint32_t smem_u32(const void* p) {
    uint32_t a;
    asm("{ .reg .u64 t; cvta.to.shared.u64 t, %1; cvt.u32.u64 %0, t; }" : "=r"(a) : "l"(p));
    return a;
}
__device__ __forceinline__ float gelu_exact(float x) {
    return 0.5f * x * (1.0f + erff(x * 0.70710678118654752f));
}
__device__ __forceinline__ void ldsm_x4(uint32_t (&r)[4], uint32_t addr) {
    asm volatile("ldmatrix.sync.aligned.m8n8.x4.shared.b16 {%0,%1,%2,%3}, [%4];"
                 : "=r"(r[0]), "=r"(r[1]), "=r"(r[2]), "=r"(r[3]) : "r"(addr));
}
__device__ __forceinline__ void ldsm_x4_t(uint32_t (&r)[4], uint32_t addr) {
    asm volatile("ldmatrix.sync.aligned.m8n8.x4.trans.shared.b16 {%0,%1,%2,%3}, [%4];"
                 : "=r"(r[0]), "=r"(r[1]), "=r"(r[2]), "=r"(r[3]) : "r"(addr));
}
__device__ __forceinline__ void mma_bf16(float (&c)[4], const uint32_t (&a)[4],
                                         const uint32_t* b) {
    asm volatile("mma.sync.aligned.m16n8k16.row.col.f32.bf16.bf16.f32 "
                 "{%0,%1,%2,%3},{%4,%5,%6,%7},{%8,%9},{%0,%1,%2,%3};"
                 : "+f"(c[0]), "+f"(c[1]), "+f"(c[2]), "+f"(c[3])
                 : "r"(a[0]), "r"(a[1]), "r"(a[2]), "r"(a[3]), "r"(b[0]), "r"(b[1]));
}
__device__ __forceinline__ void cp16(uint32_t saddr, const void* g) {
    asm volatile("cp.async.cg.shared.global [%0], [%1], 16;" :: "r"(saddr), "l"(g));
}
#define CP_COMMIT() asm volatile("cp.async.commit_group;" ::: "memory")
#define CP_WAIT1()  asm volatile("cp.async.wait_group 1;" ::: "memory")

// ---------------------------------------------------------------------------
// Precompute: Lambda_bar; weights pre-split into bf16 hi/lo.
// ---------------------------------------------------------------------------
__global__ void precompute_kernel(const float* __restrict__ lre,
                                  const float* __restrict__ lim,
                                  const float* __restrict__ Bp,
                                  const float* __restrict__ Cp,
                                  const float* __restrict__ ls) {
    int idx = blockIdx.x * blockDim.x + threadIdx.x;   // [0, 65536)
    {   // W1: p = idx>>9, hcol = idx&511
        int p = idx >> 9, hcol = idx & 511;
        float ar = lre[p], ai = lim[p];
        float st = expf(ls[p]);
        float er = expf(ar * st);
        float sb, cb; sincosf(ai * st, &sb, &cb);
        float lbr = er * cb, lbi = er * sb;
        float nr = lbr - 1.0f, ni = lbi;
        float den = ar * ar + ai * ai;
        float cr = (nr * ar + ni * ai) / den;
        float ci = (ni * ar - nr * ai) / den;
        float btr = Bp[(p * HD + hcol) * 2 + 0];
        float bti = Bp[(p * HD + hcol) * 2 + 1];
        float vre = cr * btr - ci * bti;
        float vim = cr * bti + ci * btr;
        __nv_bfloat16 h0 = __float2bfloat16_rn(vre);
        g_w1hi[p * HD + hcol] = h0;
        g_w1lo[p * HD + hcol] = __float2bfloat16_rn(vre - __bfloat162float(h0));
        __nv_bfloat16 h1 = __float2bfloat16_rn(vim);
        g_w1hi[(p + PD) * HD + hcol] = h1;
        g_w1lo[(p + PD) * HD + hcol] = __float2bfloat16_rn(vim - __bfloat162float(h1));
    }
    if (idx < PD) {
        float ar = lre[idx], ai = lim[idx];
        float st = expf(ls[idx]);
        float er = expf(ar * st);
        float sb, cb; sincosf(ai * st, &sb, &cb);
        g_lam_re[idx] = er * cb;
        g_lam_im[idx] = er * sb;
    }
    {   // W2: hrow = idx>>7, p = idx&127
        int hrow = idx >> 7, p = idx & 127;
        float vre =  2.0f * Cp[(hrow * PD + p) * 2 + 0];
        float vim = -2.0f * Cp[(hrow * PD + p) * 2 + 1];
        __nv_bfloat16 h0 = __float2bfloat16_rn(vre);
        g_w2hi[hrow * M2 + p] = h0;
        g_w2lo[hrow * M2 + p] = __float2bfloat16_rn(vre - __bfloat162float(h0));
        __nv_bfloat16 h1 = __float2bfloat16_rn(vim);
        g_w2hi[hrow * M2 + p + PD] = h1;
        g_w2lo[hrow * M2 + p + PD] = __float2bfloat16_rn(vim - __bfloat162float(h1));
    }
}

// ---------------------------------------------------------------------------
// Convert u (fp32) -> bf16 hi/lo arrays. 33.5M elems, float4 per thread.
// ---------------------------------------------------------------------------
__global__ __launch_bounds__(256)
void conv_u_kernel(const float* __restrict__ u) {
    size_t i = ((size_t)blockIdx.x * 256 + threadIdx.x) * 4;
    float4 v = *(const float4*)&u[i];
    __nv_bfloat16 h0 = __float2bfloat16_rn(v.x), h1 = __float2bfloat16_rn(v.y);
    __nv_bfloat16 h2 = __float2bfloat16_rn(v.z), h3 = __float2bfloat16_rn(v.w);
    __nv_bfloat16 l0 = __float2bfloat16_rn(v.x - __bfloat162float(h0));
    __nv_bfloat16 l1 = __float2bfloat16_rn(v.y - __bfloat162float(h1));
    __nv_bfloat16 l2 = __float2bfloat16_rn(v.z - __bfloat162float(h2));
    __nv_bfloat16 l3 = __float2bfloat16_rn(v.w - __bfloat162float(h3));
    ushort4 hw = make_ushort4(__bfloat16_as_ushort(h0), __bfloat16_as_ushort(h1),
                              __bfloat16_as_ushort(h2), __bfloat16_as_ushort(h3));
    ushort4 lw = make_ushort4(__bfloat16_as_ushort(l0), __bfloat16_as_ushort(l1),
                              __bfloat16_as_ushort(l2), __bfloat16_as_ushort(l3));
    *(ushort4*)&g_uhi[i] = hw;
    *(ushort4*)&g_ulo[i] = lw;
}

// ---------------------------------------------------------------------------
// mma.sync bf16 GEMM, 3-product split (hh+hl+lh), cp.async 3-stage pipeline.
// CTA tile 128x128, K-chunk 32, 8 warps (4m x 2n), warp tile 32x64.
// Buffer/stage: Ahi(8K) Alo(8K) Bhi(8K) Blo(8K) = 32KB; 3 stages = 96KB.
// ---------------------------------------------------------------------------
#define ABUF   8192
#define BUFSZ  32768
#define STAGES 3
#define GSMEM  (STAGES * BUFSZ)

template<bool SECOND>
__global__ __launch_bounds__(256, 2)
void mgemm_kernel(const __nv_bfloat16* __restrict__ Bhi_g,
                  const __nv_bfloat16* __restrict__ Blo_g,
                  const float* __restrict__ uin,
                  float* __restrict__ outp,
                  const float* __restrict__ Dvec) {
    constexpr int KDIM = SECOND ? M2 : HD;
    constexpr int NCH  = KDIM / 32;

    extern __shared__ __align__(128) char smem[];
    const uint32_t sbase = smem_u32(smem);

    const int tid  = threadIdx.x;
    const int wid  = tid >> 5;
    const int lane = tid & 31;
    const int warp_m = wid & 3;
    const int warp_n = wid >> 2;
    const int m0 = blockIdx.x * 128;
    const int n0 = blockIdx.y * 128;
    const int z  = blockIdx.z;

    const __nv_bfloat16* Whi = SECOND ? g_w2hi : g_w1hi;
    const __nv_bfloat16* Wlo = SECOND ? g_w2lo : g_w1lo;
    float* Cdst = SECOND ? outp : (float*)g_bu;
    const size_t Bofs = (size_t)z * KDIM * LEN;
    const size_t Cofs = (size_t)z * (SECOND ? HD : M2) * LEN;

    // staging maps (fixed per thread)
    const int sAr = tid >> 1, sAh = tid & 1;       // A: row 0..127, k-half (16 elems)
    const int sBk = tid >> 3, sBn = tid & 7;       // B: k-row 0..31, 16-wide n group
    const int aswz = (sAr >> 1) & 3;
    const int bswz = sBk & 7;
    const uint32_t aoff0 = (uint32_t)(sAr * 64 + (((sAh * 2 + 0) ^ aswz) << 4));
    const uint32_t aoff1 = (uint32_t)(sAr * 64 + (((sAh * 2 + 1) ^ aswz) << 4));
    const uint32_t boff0 = (uint32_t)(2 * ABUF + sBk * 256 + (((sBn * 2 + 0) ^ bswz) << 4));
    const uint32_t boff1 = (uint32_t)(2 * ABUF + sBk * 256 + (((sBn * 2 + 1) ^ bswz) << 4));

    auto issue_commit = [&](int ci) {
        if (ci < NCH) {
            const int k0 = ci * 32;
            const uint32_t bb = sbase + (uint32_t)(ci % STAGES) * BUFSZ;
            const __nv_bfloat16* gAh = Whi + (size_t)(m0 + sAr) * KDIM + k0 + sAh * 16;
            const __nv_bfloat16* gAl = Wlo + (size_t)(m0 + sAr) * KDIM + k0 + sAh * 16;
            cp16(bb + aoff0, gAh);
            cp16(bb + aoff1, gAh + 8);
            cp16(bb + ABUF + aoff0, gAl);
            cp16(bb + ABUF + aoff1, gAl + 8);
            const size_t go = Bofs + (size_t)(k0 + sBk) * LEN + n0 + sBn * 16;
            cp16(bb + boff0, Bhi_g + go);
            cp16(bb + boff1, Bhi_g + go + 8);
            cp16(bb + ABUF + boff0, Blo_g + go);
            cp16(bb + ABUF + boff1, Blo_g + go + 8);
        }
        CP_COMMIT();
    };

    float acc[2][8][4];
    #pragma unroll
    for (int a = 0; a < 2; a++)
        #pragma unroll
        for (int b = 0; b < 8; b++)
            #pragma unroll
            for (int c = 0; c < 4; c++) acc[a][b][c] = 0.0f;

    const int lrow8 = (lane & 7) + ((lane >> 3) & 1) * 8;   // 0..15
    const int lhalf = (lane >> 4) & 1;                      // 0/1

    auto compute = [&](uint32_t bb) {
        #pragma unroll
        for (int ks = 0; ks < 2; ks++) {
            uint32_t Ah[2][4], Al[2][4];
            #pragma unroll
            for (int mt = 0; mt < 2; mt++) {
                int row = warp_m * 32 + mt * 16 + lrow8;
                int c = ks * 2 + lhalf;
                uint32_t addr = sbase + bb + row * 64 + ((c ^ ((row >> 1) & 3)) << 4);
                ldsm_x4(Ah[mt], addr);
                ldsm_x4(Al[mt], addr + ABUF);
            }
            #pragma unroll
            for (int nt = 0; nt < 4; nt++) {
                int krow = ks * 16 + lrow8;
                int noff = warp_n * 64 + nt * 16 + lhalf * 8;
                int c = noff >> 3;
                uint32_t addr = sbase + bb + 2 * ABUF + krow * 256 +
                                ((c ^ (krow & 7)) << 4);
                uint32_t Bh[4], Bl[4];
                ldsm_x4_t(Bh, addr);
                ldsm_x4_t(Bl, addr + ABUF);
                #pragma unroll
                for (int mt = 0; mt < 2; mt++) {
                    mma_bf16(acc[mt][2*nt + 0], Ah[mt], &Bh[0]);
                    mma_bf16(acc[mt][2*nt + 0], Ah[mt], &Bl[0]);
                    mma_bf16(acc[mt][2*nt + 0], Al[mt], &Bh[0]);
                    mma_bf16(acc[mt][2*nt + 1], Ah[mt], &Bh[2]);
                    mma_bf16(acc[mt][2*nt + 1], Ah[mt], &Bl[2]);
                    mma_bf16(acc[mt][2*nt + 1], Al[mt], &Bh[2]);
                }
            }
        }
    };

    issue_commit(0);
    issue_commit(1);
    for (int i = 0; i < NCH; i++) {
        CP_WAIT1();               // group for chunk i complete
        __syncthreads();
        compute((uint32_t)(i % STAGES) * BUFSZ);
        issue_commit(i + 2);      // refills slot (i-1)%3, consumed at iter i-1
    }

    // ---------------- epilogue ----------------
    const int g = lane >> 2, t4 = lane & 3;
    #pragma unroll
    for (int mt = 0; mt < 2; mt++) {
        #pragma unroll
        for (int nt8 = 0; nt8 < 8; nt8++) {
            int col = n0 + warp_n * 64 + nt8 * 8 + t4 * 2;
            #pragma unroll
            for (int h = 0; h < 2; h++) {
                int row = m0 + warp_m * 32 + mt * 16 + g + h * 8;
                size_t off = Cofs + (size_t)row * LEN + col;
                float v0 = acc[mt][nt8][2*h + 0];
                float v1 = acc[mt][nt8][2*h + 1];
                if (SECOND) {
                    float d = __ldg(&Dvec[row]);
                    float2 uu = *(const float2*)&uin[(size_t)z * HD * LEN +
                                                     (size_t)row * LEN + col];
                    v0 = gelu_exact(v0 + d * uu.x);
                    v1 = gelu_exact(v1 + d * uu.y);
                }
                float2 st; st.x = v0; st.y = v1;
                *(float2*)&Cdst[off] = st;
            }
        }
    }
}

// ---------------------------------------------------------------------------
// Scan: x_l = a*x_{l-1} + b_l, complex diagonal, one block per (b,p) channel.
// Reads Bu fp32 from g_bu; writes xs as bf16 hi/lo for GEMM2.
// ---------------------------------------------------------------------------
__global__ __launch_bounds__(256)
void scan_kernel() {
    int ch = blockIdx.x;
    int b = ch >> 7, p = ch & 127;
    const float ar = g_lam_re[p];
    const float ai = g_lam_im[p];

    const size_t rre = ((size_t)b * M2 + p) * LEN;
    const size_t rim = ((size_t)b * M2 + p + PD) * LEN;
    const float* bre = g_bu + rre;
    const float* bim = g_bu + rim;

    __shared__ float sre[2112], sim[2112];
    __shared__ float vre[256], vim[256];
    __shared__ float carry_re, carry_im;

    int t = threadIdx.x;
    if (t == 0) { carry_re = 0.0f; carry_im = 0.0f; }

    float mr[8], mi[8];
    {
        float xr = ar, xi = ai;
        #pragma unroll
        for (int s = 0; s < 3; s++) {
            float nr = xr * xr - xi * xi;
            float ni = 2.0f * xr * xi;
            xr = nr; xi = ni;
        }
        mr[0] = xr; mi[0] = xi;
        #pragma unroll
        for (int k = 1; k < 8; k++) {
            mr[k] = mr[k-1] * mr[k-1] - mi[k-1] * mi[k-1];
            mi[k] = 2.0f * mr[k-1] * mi[k-1];
        }
    }
    __syncthreads();

    const int base = t * 8;
    for (int c0 = 0; c0 < LEN; c0 += 2048) {
        for (int j = t; j < 2048; j += 256) {
            sre[j + (j >> 5)] = bre[c0 + j];
            sim[j + (j >> 5)] = bim[c0 + j];
        }
        __syncthreads();

        float er = 0.0f, ei = 0.0f;
        if (t == 0) { er = carry_re; ei = carry_im; }
        #pragma unroll
        for (int i = 0; i < 8; i++) {
            int idx = base + i; idx += idx >> 5;
            float br = sre[idx], bi = sim[idx];
            float nr = ar * er - ai * ei + br;
            float ni = ar * ei + ai * er + bi;
            er = nr; ei = ni;
        }
        vre[t] = er; vim[t] = ei;
        __syncthreads();

        #pragma unroll
        for (int k = 0; k < 8; k++) {
            int off = 1 << k;
            float pr = 0.0f, pi = 0.0f;
            if (t >= off) { pr = vre[t - off]; pi = vim[t - off]; }
            __syncthreads();
            if (t >= off) {
                vre[t] += mr[k] * pr - mi[k] * pi;
                vim[t] += mr[k] * pi + mi[k] * pr;
            }
            __syncthreads();
        }

        float xr, xi;
        if (t == 0) { xr = carry_re; xi = carry_im; }
        else        { xr = vre[t-1]; xi = vim[t-1]; }
        #pragma unroll
        for (int i = 0; i < 8; i++) {
            int idx = base + i; idx += idx >> 5;
            float br = sre[idx], bi = sim[idx];
            float nr = ar * xr - ai * xi + br;
            float ni = ar * xi + ai * xr + bi;
            xr = nr; xi = ni;
            sre[idx] = xr; sim[idx] = xi;
        }
        __syncthreads();

        if (t == 0) { carry_re = vre[255]; carry_im = vim[255]; }
        // writeback: convert to bf16 hi/lo
        for (int j = t; j < 2048; j += 256) {
            float xr2 = sre[j + (j >> 5)];
            float xi2 = sim[j + (j >> 5)];
            __nv_bfloat16 hr = __float2bfloat16_rn(xr2);
            __nv_bfloat16 hi = __float2bfloat16_rn(xi2);
            g_xhi[rre + c0 + j] = hr;
            g_xhi[rim + c0 + j] = hi;
            g_xlo[rre + c0 + j] = __float2bfloat16_rn(xr2 - __bfloat162float(hr));
            g_xlo[rim + c0 + j] = __float2bfloat16_rn(xi2 - __bfloat162float(hi));
        }
        __syncthreads();
    }
}

// ---------------------------------------------------------------------------
extern "C" void kernel_launch(void* const* d_in, const int* in_sizes, int n_in,
                              void* d_out, int out_size) {
    const float* u   = (const float*)d_in[0];   // (8,1,512,1,8192)
    const float* lre = (const float*)d_in[1];
    const float* lim = (const float*)d_in[2];
    const float* B   = (const float*)d_in[3];
    const float* C   = (const float*)d_in[4];
    const float* D   = (const float*)d_in[5];
    const float* ls  = (const float*)d_in[6];
    float* out = (float*)d_out;

    cudaFuncSetAttribute(mgemm_kernel<false>,
                         cudaFuncAttributeMaxDynamicSharedMemorySize, GSMEM);
    cudaFuncSetAttribute(mgemm_kernel<true>,
                         cudaFuncAttributeMaxDynamicSharedMemorySize, GSMEM);

    __nv_bfloat16 *uhi, *ulo, *xhi, *xlo;
    cudaGetSymbolAddress((void**)&uhi, g_uhi);
    cudaGetSymbolAddress((void**)&ulo, g_ulo);
    cudaGetSymbolAddress((void**)&xhi, g_xhi);
    cudaGetSymbolAddress((void**)&xlo, g_xlo);

    precompute_kernel<<<256, 256>>>(lre, lim, B, C, ls);
    conv_u_kernel<<<32768, 256>>>(u);   // 32768*256*4 = 33.5M = BSZN*HD*LEN
    mgemm_kernel<false><<<dim3(2, 64, BSZN), 256, GSMEM>>>(uhi, ulo, u, nullptr, nullptr);
    scan_kernel<<<1024, 256>>>();
    mgemm_kernel<true><<<dim3(4, 64, BSZN), 256, GSMEM>>>(xhi, xlo, u, out, D);
}